// round 15
// baseline (speedup 1.0000x reference)
#include <cuda_runtime.h>
#include <cuda_fp16.h>
#include <cstdint>

#define N_EXPERTS 8
#define N_EMBED   1024
#define NTOK      4096
#define TOPK      2
#define NROWS     (NTOK*TOPK)
#define MAXCAP    NROWS

#define BM 64
#define BN 128
#define BK 64
#define NK (N_EMBED/BK)        // 16 k-iterations
#define RSTRIDE 144            // 128B row + 16B pad: 9x16B, gcd(9,8)=1 -> conflict-free
#define STAGES 2

#define SOFF_STAGE  1024
#define MAT_A       (64*RSTRIDE)             // 9216
#define STAGE_BYTES ((64+128)*RSTRIDE)       // 27648
#define SMEM_BYTES  (SOFF_STAGE + STAGES*STAGE_BYTES)  // 56320

// ---- scratch (device globals; no allocations allowed) ----
__device__ int   g_counts[N_EXPERTS];
__device__ int   g_list[N_EXPERTS * MAXCAP];
__device__ float g_probs[NTOK * TOPK];
__device__ __align__(16) float  g_outbuf[(size_t)NROWS * N_EMBED];
__device__ __align__(16) __half g_xhi[(size_t)NTOK * N_EMBED];
__device__ __align__(16) __half g_whi[(size_t)N_EXPERTS*N_EMBED*N_EMBED];  // [e][o][i]

// ------------------------------------------------------------------ helpers
__device__ __forceinline__ uint32_t smem_u32(const void* p) {
    uint32_t a;
    asm("{ .reg .u64 t; cvta.to.shared.u64 t, %1; cvt.u32.u64 %0, t; }"
        : "=r"(a) : "l"(p));
    return a;
}
__device__ __forceinline__ void cp16(uint32_t dst, const void* src, int srcsz) {
    asm volatile("cp.async.cg.shared.global [%0], [%1], 16, %2;"
                 :: "r"(dst), "l"(src), "r"(srcsz) : "memory");
}
__device__ __forceinline__ void ldsm4(uint32_t* r, uint32_t addr) {
    asm volatile("ldmatrix.sync.aligned.m8n8.x4.shared.b16 {%0,%1,%2,%3}, [%4];"
                 : "=r"(r[0]), "=r"(r[1]), "=r"(r[2]), "=r"(r[3]) : "r"(addr));
}
__device__ __forceinline__ void mma16816(float* c, const uint32_t* a, const uint32_t* b) {
    asm volatile("mma.sync.aligned.m16n8k16.row.col.f32.f16.f16.f32 "
                 "{%0,%1,%2,%3}, {%4,%5,%6,%7}, {%8,%9}, {%0,%1,%2,%3};"
                 : "+f"(c[0]), "+f"(c[1]), "+f"(c[2]), "+f"(c[3])
                 : "r"(a[0]), "r"(a[1]), "r"(a[2]), "r"(a[3]), "r"(b[0]), "r"(b[1]));
}

// ------------------------------------------------------------------
__global__ void init_kernel() {
    if (threadIdx.x < N_EXPERTS) g_counts[threadIdx.x] = 0;
}

// ------------------------------------------------------------------ gate v3: 16 tokens/block, batched atomics  [R10 verbatim]
__global__ __launch_bounds__(256) void gate_convert_kernel(
    const float* __restrict__ x,
    const float* __restrict__ wg,
    const float* __restrict__ bias,
    float* __restrict__ probs_out)
{
    __shared__ int sassign[16];
    int tid = threadIdx.x;
    int tg  = tid >> 4;
    int s   = tid & 15;
    int token0 = blockIdx.x * 16;
    int token  = token0 + tg;

    const float4* xr = (const float4*)(x + (size_t)token * N_EMBED);
    uint2* xo = (uint2*)g_xhi + (size_t)token * 256;

    float acc[N_EXPERTS];
#pragma unroll
    for (int e = 0; e < N_EXPERTS; e++) acc[e] = 0.f;

#pragma unroll
    for (int i = 0; i < 16; i++) {
        int p = s + 16 * i;
        float4 v = xr[p];
        float vv[4] = {v.x, v.y, v.z, v.w};
        uint32_t h0 = (uint32_t)__half_as_ushort(__float2half(vv[0]))
                    | ((uint32_t)__half_as_ushort(__float2half(vv[1])) << 16);
        uint32_t h1 = (uint32_t)__half_as_ushort(__float2half(vv[2]))
                    | ((uint32_t)__half_as_ushort(__float2half(vv[3])) << 16);
        xo[p] = make_uint2(h0, h1);
#pragma unroll
        for (int q = 0; q < 4; q++) {
            const float* wr = wg + (p * 4 + q) * N_EXPERTS;
            float xv = vv[q];
#pragma unroll
            for (int e = 0; e < N_EXPERTS; e++) acc[e] += xv * wr[e];
        }
    }
#pragma unroll
    for (int off = 8; off > 0; off >>= 1) {
#pragma unroll
        for (int e = 0; e < N_EXPERTS; e++)
            acc[e] += __shfl_down_sync(0xffffffffu, acc[e], off, 16);
    }

    if (s == 0) {
        float fin[N_EXPERTS];
#pragma unroll
        for (int e = 0; e < N_EXPERTS; e++) fin[e] = acc[e] + bias[e];
        int e0 = 0; float v0 = fin[0];
#pragma unroll
        for (int e = 1; e < N_EXPERTS; e++)
            if (fin[e] > v0) { v0 = fin[e]; e0 = e; }
        int e1 = -1; float v1 = -3.0e38f;
#pragma unroll
        for (int e = 0; e < N_EXPERTS; e++)
            if (e != e0 && fin[e] > v1) { v1 = fin[e]; e1 = e; }

        float ex  = expf(v1 - v0);
        float inv = 1.0f / (1.0f + ex);
        float p0 = inv, p1 = ex * inv;

        g_probs[token * 2 + 0] = p0;
        g_probs[token * 2 + 1] = p1;
        if (probs_out) {
            probs_out[token * 2 + 0] = p0;
            probs_out[token * 2 + 1] = p1;
        }
        sassign[tg] = e0 | (e1 << 8);
    }
    __syncthreads();

    if (tid < N_EXPERTS) {
        int cnt = 0;
#pragma unroll
        for (int t = 0; t < 16; t++) {
            int a = sassign[t];
            cnt += ((a & 0xFF) == tid) + (((a >> 8) & 0xFF) == tid);
        }
        int base = atomicAdd(&g_counts[tid], cnt);
#pragma unroll
        for (int t = 0; t < 16; t++) {
            int a = sassign[t];
            if ((a & 0xFF) == tid)        g_list[tid * MAXCAP + base++] = (token0 + t) * 2;
            if (((a >> 8) & 0xFF) == tid) g_list[tid * MAXCAP + base++] = (token0 + t) * 2 + 1;
        }
    }
}

// ------------------------------------------------------------------ W[e][i][o] -> fp16 transposed [e][o][i]  [R10 verbatim]
__global__ __launch_bounds__(256) void convert_w_kernel(const float* __restrict__ w)
{
    __shared__ float sm[32][33];
    int e  = blockIdx.z;
    int i0 = blockIdx.x * 32;
    int o0 = blockIdx.y * 32;
    int tx = threadIdx.x, ty = threadIdx.y;   // (32, 8)

#pragma unroll
    for (int r = 0; r < 4; r++) {
        int i = i0 + ty + r * 8;
        sm[ty + r * 8][tx] = w[((size_t)e * N_EMBED + i) * N_EMBED + o0 + tx];
    }
    __syncthreads();
#pragma unroll
    for (int r = 0; r < 4; r++) {
        int o = o0 + ty + r * 8;
        float v = sm[tx][ty + r * 8];
        g_whi[((size_t)e * N_EMBED + o) * N_EMBED + i0 + tx] = __float2half(v);
    }
}

// ------------------------------------------------------------------ grouped GEMM: 64x128 tile, 256 threads, 8 warps of 32x32  [R9/R10 mainloop]
__global__ void __launch_bounds__(256, 3) gemm_tc_kernel()
{
    extern __shared__ __align__(128) char smem[];
    int e   = blockIdx.z;
    int cnt = g_counts[e];
    int m0  = blockIdx.y * BM;
    if (m0 >= cnt) return;
    int n0  = blockIdx.x * BN;
    int tid = threadIdx.x, lane = tid & 31, wid = tid >> 5;
    int wm  = wid & 1;
    int wn  = wid >> 1;

    uint32_t sbase = smem_u32(smem);
    int* rows_s = (int*)smem;
    if (tid < BM) {
        int r = m0 + tid;
        rows_s[tid] = (r < cnt) ? g_list[e * MAXCAP + r] : -1;
    }
    __syncthreads();

    int r8 = tid >> 3, q = tid & 7;
    int arow0 = rows_s[r8], arow1 = rows_s[r8 + 32];
    int tok0 = (arow0 >= 0) ? (arow0 >> 1) : 0;
    int tok1 = (arow1 >= 0) ? (arow1 >> 1) : 0;
    int ap0 = (arow0 >= 0) ? 16 : 0;
    int ap1 = (arow1 >= 0) ? 16 : 0;
    const __half* aSrc0 = g_xhi + (size_t)tok0 * N_EMBED + q * 8;
    const __half* aSrc1 = g_xhi + (size_t)tok1 * N_EMBED + q * 8;
    const __half* bSrc  = g_whi + ((size_t)(e * N_EMBED + n0 + r8)) * N_EMBED + q * 8;
    uint32_t dstA = (uint32_t)(r8 * RSTRIDE + q * 16);
    uint32_t dstB = (uint32_t)(MAT_A + r8 * RSTRIDE + q * 16);

    uint32_t aAddr = sbase + SOFF_STAGE
                   + (uint32_t)((wm * 32 + (lane & 15)) * RSTRIDE + (lane >> 4) * 16);
    uint32_t bAddr = sbase + SOFF_STAGE + MAT_A
                   + (uint32_t)((wn * 32 + ((lane >> 4) << 3) + (lane & 7)) * RSTRIDE
                                + ((lane >> 3) & 1) * 16);

    float c[2][4][4];
#pragma unroll
    for (int mi = 0; mi < 2; mi++)
#pragma unroll
        for (int ni = 0; ni < 4; ni++)
#pragma unroll
            for (int r = 0; r < 4; r++) c[mi][ni][r] = 0.f;

    auto issue = [&](int it) {
        uint32_t st = sbase + SOFF_STAGE + (uint32_t)((it & 1) * STAGE_BYTES);
        int kt = it * BK;
        cp16(st + dstA,                aSrc0 + kt, ap0);
        cp16(st + dstA + 32 * RSTRIDE, aSrc1 + kt, ap1);
#pragma unroll
        for (int k = 0; k < 4; k++)
            cp16(st + dstB + (uint32_t)(k * 32 * RSTRIDE),
                 bSrc + kt + (size_t)k * 32 * N_EMBED, 16);
        asm volatile("cp.async.commit_group;" ::: "memory");
    };

    issue(0);
    issue(1);

    for (int it = 0; it < NK; it++) {
        if (it + 1 < NK) asm volatile("cp.async.wait_group 1;" ::: "memory");
        else             asm volatile("cp.async.wait_group 0;" ::: "memory");
        __syncthreads();

        uint32_t stA = (uint32_t)((it & 1) * STAGE_BYTES);
#pragma unroll
        for (int kk = 0; kk < 4; kk++) {
            uint32_t ko = (uint32_t)(kk * 32);
            uint32_t ah[2][4];
#pragma unroll
            for (int mi = 0; mi < 2; mi++)
                ldsm4(ah[mi], aAddr + stA + (uint32_t)(mi * 16 * RSTRIDE) + ko);
#pragma unroll
            for (int pr = 0; pr < 2; pr++) {
                uint32_t bh[4];
                ldsm4(bh, bAddr + stA + (uint32_t)(pr * 16 * RSTRIDE) + ko);
#pragma unroll
                for (int mi = 0; mi < 2; mi++) {
#pragma unroll
                    for (int t = 0; t < 2; t++) {
                        mma16816(c[mi][pr * 2 + t], ah[mi], &bh[t * 2]);
                    }
                }
            }
        }
        __syncthreads();
        if (it + 2 < NK) issue(it + 2);
    }

#pragma unroll
    for (int mi = 0; mi < 2; mi++) {
#pragma unroll
        for (int h = 0; h < 2; h++) {
            int r = wm * 32 + mi * 16 + (lane >> 2) + h * 8;
            if (m0 + r < cnt) {
                int rowid = rows_s[r];
                float* dst = g_outbuf + (size_t)rowid * N_EMBED
                           + n0 + wn * 32 + (lane & 3) * 2;
#pragma unroll
                for (int ni = 0; ni < 4; ni++) {
                    float2 v = make_float2(c[mi][ni][h * 2 + 0], c[mi][ni][h * 2 + 1]);
                    *(float2*)(dst + ni * 8) = v;
                }
            }
        }
    }
}

// ------------------------------------------------------------------ combine  [R10 verbatim]
__global__ __launch_bounds__(256) void combine_kernel(float* __restrict__ y)
{
    int token = blockIdx.x;
    int tid   = threadIdx.x;
    float p0 = g_probs[token * 2 + 0];
    float p1 = g_probs[token * 2 + 1];
    const float4* o0 = (const float4*)(g_outbuf + (size_t)(token * 2) * N_EMBED);
    const float4* o1 = o0 + (N_EMBED / 4);
    float4 a = o0[tid];
    float4 b = o1[tid];
    float4 r = make_float4(p0 * a.x + p1 * b.x,
                           p0 * a.y + p1 * b.y,
                           p0 * a.z + p1 * b.z,
                           p0 * a.w + p1 * b.w);
    ((float4*)(y + (size_t)token * N_EMBED))[tid] = r;
}

// ------------------------------------------------------------------
extern "C" void kernel_launch(void* const* d_in, const int* in_sizes, int n_in,
                              void* d_out, int out_size)
{
    const float* x    = (const float*)d_in[0];
    const float* wg   = (const float*)d_in[1];
    const float* bias = (const float*)d_in[2];
    const float* w    = (const float*)d_in[3];
    float* out = (float*)d_out;

    const int Y_ELEMS = NTOK * N_EMBED;
    float* probs_out = (out_size >= Y_ELEMS + NTOK * TOPK) ? (out + Y_ELEMS) : nullptr;

    cudaFuncSetAttribute(gemm_tc_kernel,
                         cudaFuncAttributeMaxDynamicSharedMemorySize, SMEM_BYTES);

    init_kernel<<<1, 32>>>();
    gate_convert_kernel<<<NTOK / 16, 256>>>(x, wg, bias, probs_out);
    convert_w_kernel<<<dim3(32, 32, N_EXPERTS), dim3(32, 8)>>>(w);

    dim3 grid(N_EMBED / BN, MAXCAP / BM, N_EXPERTS);   // (8, 128, 8)
    gemm_tc_kernel<<<grid, 256, SMEM_BYTES>>>();

    combine_kernel<<<NTOK, 256>>>(out);
}

// round 16
// speedup vs baseline: 1.7361x; 1.7361x over previous
#include <cuda_runtime.h>
#include <cuda_fp16.h>
#include <cstdint>

#define N_EXPERTS 8
#define N_EMBED   1024
#define NTOK      4096
#define TOPK      2
#define NROWS     (NTOK*TOPK)
#define MAXCAP    NROWS

#define BM 64
#define BN 128
#define BK 64
#define NK (N_EMBED/BK)        // 16 k-iterations
#define RSTRIDE 144            // 128B row + 16B pad: 9x16B, gcd(9,8)=1 -> conflict-free
#define STAGES 2
#define MAXTILES 136           // sum ceil(cnt_e/BM) <= 128+8

#define SOFF_STAGE  1024
#define MAT_A       (64*RSTRIDE)             // 9216
#define STAGE_BYTES ((64+128)*RSTRIDE)       // 27648
#define SMEM_BYTES  (SOFF_STAGE + STAGES*STAGE_BYTES)  // 56320

// ---- scratch (device globals; no allocations allowed) ----
__device__ int   g_counts[N_EXPERTS];
__device__ int   g_list[N_EXPERTS * MAXCAP];
__device__ int2  g_tilemap[MAXTILES];
__device__ float g_probs[NTOK * TOPK];
__device__ __align__(16) float  g_outbuf[(size_t)NROWS * N_EMBED];
__device__ __align__(16) __half g_xhi[(size_t)NTOK * N_EMBED];
__device__ __align__(16) __half g_whi[(size_t)N_EXPERTS*N_EMBED*N_EMBED];  // [e][o][i]

// ------------------------------------------------------------------ helpers
__device__ __forceinline__ uint32_t smem_u32(const void* p) {
    uint32_t a;
    asm("{ .reg .u64 t; cvta.to.shared.u64 t, %1; cvt.u32.u64 %0, t; }"
        : "=r"(a) : "l"(p));
    return a;
}
__device__ __forceinline__ void cp16(uint32_t dst, const void* src, int srcsz) {
    asm volatile("cp.async.ca.shared.global [%0], [%1], 16, %2;"
                 :: "r"(dst), "l"(src), "r"(srcsz) : "memory");
}
__device__ __forceinline__ void ldsm4(uint32_t* r, uint32_t addr) {
    asm volatile("ldmatrix.sync.aligned.m8n8.x4.shared.b16 {%0,%1,%2,%3}, [%4];"
                 : "=r"(r[0]), "=r"(r[1]), "=r"(r[2]), "=r"(r[3]) : "r"(addr));
}
__device__ __forceinline__ void mma16816(float* c, const uint32_t* a, const uint32_t* b) {
    asm volatile("mma.sync.aligned.m16n8k16.row.col.f32.f16.f16.f32 "
                 "{%0,%1,%2,%3}, {%4,%5,%6,%7}, {%8,%9}, {%0,%1,%2,%3};"
                 : "+f"(c[0]), "+f"(c[1]), "+f"(c[2]), "+f"(c[3])
                 : "r"(a[0]), "r"(a[1]), "r"(a[2]), "r"(a[3]), "r"(b[0]), "r"(b[1]));
}

// ------------------------------------------------------------------
__global__ void init_kernel() {
    if (threadIdx.x < N_EXPERTS) g_counts[threadIdx.x] = 0;
}

// ------------------------------------------------------------------ build compact tile table (1 warp; runs after gate)
__global__ void tilemap_kernel() {
    if (threadIdx.x == 0) {
        int t = 0;
#pragma unroll
        for (int e = 0; e < N_EXPERTS; e++) {
            int cnt = g_counts[e];
            for (int m0 = 0; m0 < cnt; m0 += BM)
                g_tilemap[t++] = make_int2(e, m0);
        }
        for (; t < MAXTILES; t++)
            g_tilemap[t] = make_int2(-1, 0);
    }
}

// ------------------------------------------------------------------ gate v3: 16 tokens/block, batched atomics  [R10 verbatim]
__global__ __launch_bounds__(256) void gate_convert_kernel(
    const float* __restrict__ x,
    const float* __restrict__ wg,
    const float* __restrict__ bias,
    float* __restrict__ probs_out)
{
    __shared__ int sassign[16];
    int tid = threadIdx.x;
    int tg  = tid >> 4;
    int s   = tid & 15;
    int token0 = blockIdx.x * 16;
    int token  = token0 + tg;

    const float4* xr = (const float4*)(x + (size_t)token * N_EMBED);
    uint2* xo = (uint2*)g_xhi + (size_t)token * 256;

    float acc[N_EXPERTS];
#pragma unroll
    for (int e = 0; e < N_EXPERTS; e++) acc[e] = 0.f;

#pragma unroll
    for (int i = 0; i < 16; i++) {
        int p = s + 16 * i;
        float4 v = xr[p];
        float vv[4] = {v.x, v.y, v.z, v.w};
        uint32_t h0 = (uint32_t)__half_as_ushort(__float2half(vv[0]))
                    | ((uint32_t)__half_as_ushort(__float2half(vv[1])) << 16);
        uint32_t h1 = (uint32_t)__half_as_ushort(__float2half(vv[2]))
                    | ((uint32_t)__half_as_ushort(__float2half(vv[3])) << 16);
        xo[p] = make_uint2(h0, h1);
#pragma unroll
        for (int q = 0; q < 4; q++) {
            const float* wr = wg + (p * 4 + q) * N_EXPERTS;
            float xv = vv[q];
#pragma unroll
            for (int e = 0; e < N_EXPERTS; e++) acc[e] += xv * wr[e];
        }
    }
#pragma unroll
    for (int off = 8; off > 0; off >>= 1) {
#pragma unroll
        for (int e = 0; e < N_EXPERTS; e++)
            acc[e] += __shfl_down_sync(0xffffffffu, acc[e], off, 16);
    }

    if (s == 0) {
        float fin[N_EXPERTS];
#pragma unroll
        for (int e = 0; e < N_EXPERTS; e++) fin[e] = acc[e] + bias[e];
        int e0 = 0; float v0 = fin[0];
#pragma unroll
        for (int e = 1; e < N_EXPERTS; e++)
            if (fin[e] > v0) { v0 = fin[e]; e0 = e; }
        int e1 = -1; float v1 = -3.0e38f;
#pragma unroll
        for (int e = 0; e < N_EXPERTS; e++)
            if (e != e0 && fin[e] > v1) { v1 = fin[e]; e1 = e; }

        float ex  = expf(v1 - v0);
        float inv = 1.0f / (1.0f + ex);
        float p0 = inv, p1 = ex * inv;

        g_probs[token * 2 + 0] = p0;
        g_probs[token * 2 + 1] = p1;
        if (probs_out) {
            probs_out[token * 2 + 0] = p0;
            probs_out[token * 2 + 1] = p1;
        }
        sassign[tg] = e0 | (e1 << 8);
    }
    __syncthreads();

    if (tid < N_EXPERTS) {
        int cnt = 0;
#pragma unroll
        for (int t = 0; t < 16; t++) {
            int a = sassign[t];
            cnt += ((a & 0xFF) == tid) + (((a >> 8) & 0xFF) == tid);
        }
        int base = atomicAdd(&g_counts[tid], cnt);
#pragma unroll
        for (int t = 0; t < 16; t++) {
            int a = sassign[t];
            if ((a & 0xFF) == tid)        g_list[tid * MAXCAP + base++] = (token0 + t) * 2;
            if (((a >> 8) & 0xFF) == tid) g_list[tid * MAXCAP + base++] = (token0 + t) * 2 + 1;
        }
    }
}

// ------------------------------------------------------------------ W[e][i][o] -> fp16 transposed [e][o][i]  [R10 verbatim]
__global__ __launch_bounds__(256) void convert_w_kernel(const float* __restrict__ w)
{
    __shared__ float sm[32][33];
    int e  = blockIdx.z;
    int i0 = blockIdx.x * 32;
    int o0 = blockIdx.y * 32;
    int tx = threadIdx.x, ty = threadIdx.y;   // (32, 8)

#pragma unroll
    for (int r = 0; r < 4; r++) {
        int i = i0 + ty + r * 8;
        sm[ty + r * 8][tx] = w[((size_t)e * N_EMBED + i) * N_EMBED + o0 + tx];
    }
    __syncthreads();
#pragma unroll
    for (int r = 0; r < 4; r++) {
        int o = o0 + ty + r * 8;
        float v = sm[tx][ty + r * 8];
        g_whi[((size_t)e * N_EMBED + o) * N_EMBED + i0 + tx] = __float2half(v);
    }
}

// ------------------------------------------------------------------ grouped GEMM: 64x128 tile, 256 threads, 8 warps of 32x32
// [R10 mainloop verbatim; block -> tile via compact tilemap]
__global__ void __launch_bounds__(256, 3) gemm_tc_kernel()
{
    extern __shared__ __align__(128) char smem[];
    int2 tm = g_tilemap[blockIdx.y];
    int e   = tm.x;
    if (e < 0) return;
    int m0  = tm.y;
    int cnt = g_counts[e];
    int n0  = blockIdx.x * BN;
    int tid = threadIdx.x, lane = tid & 31, wid = tid >> 5;
    int wm  = wid & 1;
    int wn  = wid >> 1;

    uint32_t sbase = smem_u32(smem);
    int* rows_s = (int*)smem;
    if (tid < BM) {
        int r = m0 + tid;
        rows_s[tid] = (r < cnt) ? g_list[e * MAXCAP + r] : -1;
    }
    __syncthreads();

    int r8 = tid >> 3, q = tid & 7;
    int arow0 = rows_s[r8], arow1 = rows_s[r8 + 32];
    int tok0 = (arow0 >= 0) ? (arow0 >> 1) : 0;
    int tok1 = (arow1 >= 0) ? (arow1 >> 1) : 0;
    int ap0 = (arow0 >= 0) ? 16 : 0;
    int ap1 = (arow1 >= 0) ? 16 : 0;
    const __half* aSrc0 = g_xhi + (size_t)tok0 * N_EMBED + q * 8;
    const __half* aSrc1 = g_xhi + (size_t)tok1 * N_EMBED + q * 8;
    const __half* bSrc  = g_whi + ((size_t)(e * N_EMBED + n0 + r8)) * N_EMBED + q * 8;
    uint32_t dstA = (uint32_t)(r8 * RSTRIDE + q * 16);
    uint32_t dstB = (uint32_t)(MAT_A + r8 * RSTRIDE + q * 16);

    uint32_t aAddr = sbase + SOFF_STAGE
                   + (uint32_t)((wm * 32 + (lane & 15)) * RSTRIDE + (lane >> 4) * 16);
    uint32_t bAddr = sbase + SOFF_STAGE + MAT_A
                   + (uint32_t)((wn * 32 + ((lane >> 4) << 3) + (lane & 7)) * RSTRIDE
                                + ((lane >> 3) & 1) * 16);

    float c[2][4][4];
#pragma unroll
    for (int mi = 0; mi < 2; mi++)
#pragma unroll
        for (int ni = 0; ni < 4; ni++)
#pragma unroll
            for (int r = 0; r < 4; r++) c[mi][ni][r] = 0.f;

    auto issue = [&](int it) {
        uint32_t st = sbase + SOFF_STAGE + (uint32_t)((it & 1) * STAGE_BYTES);
        int kt = it * BK;
        cp16(st + dstA,                aSrc0 + kt, ap0);
        cp16(st + dstA + 32 * RSTRIDE, aSrc1 + kt, ap1);
#pragma unroll
        for (int k = 0; k < 4; k++)
            cp16(st + dstB + (uint32_t)(k * 32 * RSTRIDE),
                 bSrc + kt + (size_t)k * 32 * N_EMBED, 16);
        asm volatile("cp.async.commit_group;" ::: "memory");
    };

    issue(0);
    issue(1);

    for (int it = 0; it < NK; it++) {
        if (it + 1 < NK) asm volatile("cp.async.wait_group 1;" ::: "memory");
        else             asm volatile("cp.async.wait_group 0;" ::: "memory");
        __syncthreads();

        uint32_t stA = (uint32_t)((it & 1) * STAGE_BYTES);
#pragma unroll
        for (int kk = 0; kk < 4; kk++) {
            uint32_t ko = (uint32_t)(kk * 32);
            uint32_t ah[2][4];
#pragma unroll
            for (int mi = 0; mi < 2; mi++)
                ldsm4(ah[mi], aAddr + stA + (uint32_t)(mi * 16 * RSTRIDE) + ko);
#pragma unroll
            for (int pr = 0; pr < 2; pr++) {
                uint32_t bh[4];
                ldsm4(bh, bAddr + stA + (uint32_t)(pr * 16 * RSTRIDE) + ko);
#pragma unroll
                for (int mi = 0; mi < 2; mi++) {
#pragma unroll
                    for (int t = 0; t < 2; t++) {
                        mma16816(c[mi][pr * 2 + t], ah[mi], &bh[t * 2]);
                    }
                }
            }
        }
        __syncthreads();
        if (it + 2 < NK) issue(it + 2);
    }

#pragma unroll
    for (int mi = 0; mi < 2; mi++) {
#pragma unroll
        for (int h = 0; h < 2; h++) {
            int r = wm * 32 + mi * 16 + (lane >> 2) + h * 8;
            if (m0 + r < cnt) {
                int rowid = rows_s[r];
                float* dst = g_outbuf + (size_t)rowid * N_EMBED
                           + n0 + wn * 32 + (lane & 3) * 2;
#pragma unroll
                for (int ni = 0; ni < 4; ni++) {
                    float2 v = make_float2(c[mi][ni][h * 2 + 0], c[mi][ni][h * 2 + 1]);
                    *(float2*)(dst + ni * 8) = v;
                }
            }
        }
    }
}

// ------------------------------------------------------------------ combine  [R10 verbatim]
__global__ __launch_bounds__(256) void combine_kernel(float* __restrict__ y)
{
    int token = blockIdx.x;
    int tid   = threadIdx.x;
    float p0 = g_probs[token * 2 + 0];
    float p1 = g_probs[token * 2 + 1];
    const float4* o0 = (const float4*)(g_outbuf + (size_t)(token * 2) * N_EMBED);
    const float4* o1 = o0 + (N_EMBED / 4);
    float4 a = o0[tid];
    float4 b = o1[tid];
    float4 r = make_float4(p0 * a.x + p1 * b.x,
                           p0 * a.y + p1 * b.y,
                           p0 * a.z + p1 * b.z,
                           p0 * a.w + p1 * b.w);
    ((float4*)(y + (size_t)token * N_EMBED))[tid] = r;
}

// ------------------------------------------------------------------
extern "C" void kernel_launch(void* const* d_in, const int* in_sizes, int n_in,
                              void* d_out, int out_size)
{
    const float* x    = (const float*)d_in[0];
    const float* wg   = (const float*)d_in[1];
    const float* bias = (const float*)d_in[2];
    const float* w    = (const float*)d_in[3];
    float* out = (float*)d_out;

    const int Y_ELEMS = NTOK * N_EMBED;
    float* probs_out = (out_size >= Y_ELEMS + NTOK * TOPK) ? (out + Y_ELEMS) : nullptr;

    cudaFuncSetAttribute(gemm_tc_kernel,
                         cudaFuncAttributeMaxDynamicSharedMemorySize, SMEM_BYTES);

    init_kernel<<<1, 32>>>();
    gate_convert_kernel<<<NTOK / 16, 256>>>(x, wg, bias, probs_out);
    tilemap_kernel<<<1, 32>>>();
    convert_w_kernel<<<dim3(32, 32, N_EXPERTS), dim3(32, 8)>>>(w);

    dim3 grid(N_EMBED / BN, MAXTILES);   // (8, 136) — all-useful blocks
    gemm_tc_kernel<<<grid, 256, SMEM_BYTES>>>();

    combine_kernel<<<NTOK, 256>>>(out);
}

// round 17
// speedup vs baseline: 1.7793x; 1.0249x over previous
#include <cuda_runtime.h>
#include <cuda_fp16.h>
#include <cstdint>

#define N_EXPERTS 8
#define N_EMBED   1024
#define NTOK      4096
#define TOPK      2
#define NROWS     (NTOK*TOPK)
#define MAXCAP    NROWS

#define BM 64
#define BN 128
#define BK 64
#define NK (N_EMBED/BK)        // 16 k-iterations
#define RSTRIDE 144            // 128B row + 16B pad: 9x16B, gcd(9,8)=1 -> conflict-free
#define STAGES 2

#define SOFF_STAGE  1024
#define MAT_A       (64*RSTRIDE)             // 9216
#define STAGE_BYTES ((64+128)*RSTRIDE)       // 27648
#define SMEM_BYTES  (SOFF_STAGE + STAGES*STAGE_BYTES)  // 56320

// ---- scratch (device globals; no allocations allowed) ----
__device__ int   g_counts[N_EXPERTS];
__device__ int   g_list[N_EXPERTS * MAXCAP];
__device__ float g_probs[NTOK * TOPK];
__device__ __align__(16) __half g_outbuf[(size_t)NROWS * N_EMBED];   // fp16 now (16.8MB)
__device__ __align__(16) __half g_xhi[(size_t)NTOK * N_EMBED];
__device__ __align__(16) __half g_whi[(size_t)N_EXPERTS*N_EMBED*N_EMBED];  // [e][o][i]

// ------------------------------------------------------------------ helpers
__device__ __forceinline__ uint32_t smem_u32(const void* p) {
    uint32_t a;
    asm("{ .reg .u64 t; cvta.to.shared.u64 t, %1; cvt.u32.u64 %0, t; }"
        : "=r"(a) : "l"(p));
    return a;
}
__device__ __forceinline__ void cp16(uint32_t dst, const void* src, int srcsz) {
    asm volatile("cp.async.ca.shared.global [%0], [%1], 16, %2;"
                 :: "r"(dst), "l"(src), "r"(srcsz) : "memory");
}
__device__ __forceinline__ void ldsm4(uint32_t* r, uint32_t addr) {
    asm volatile("ldmatrix.sync.aligned.m8n8.x4.shared.b16 {%0,%1,%2,%3}, [%4];"
                 : "=r"(r[0]), "=r"(r[1]), "=r"(r[2]), "=r"(r[3]) : "r"(addr));
}
__device__ __forceinline__ void mma16816(float* c, const uint32_t* a, const uint32_t* b) {
    asm volatile("mma.sync.aligned.m16n8k16.row.col.f32.f16.f16.f32 "
                 "{%0,%1,%2,%3}, {%4,%5,%6,%7}, {%8,%9}, {%0,%1,%2,%3};"
                 : "+f"(c[0]), "+f"(c[1]), "+f"(c[2]), "+f"(c[3])
                 : "r"(a[0]), "r"(a[1]), "r"(a[2]), "r"(a[3]), "r"(b[0]), "r"(b[1]));
}

// ------------------------------------------------------------------
__global__ void init_kernel() {
    if (threadIdx.x < N_EXPERTS) g_counts[threadIdx.x] = 0;
}

// ------------------------------------------------------------------ gate v3: 16 tokens/block, batched atomics  [R10 verbatim]
__global__ __launch_bounds__(256) void gate_convert_kernel(
    const float* __restrict__ x,
    const float* __restrict__ wg,
    const float* __restrict__ bias,
    float* __restrict__ probs_out)
{
    __shared__ int sassign[16];
    int tid = threadIdx.x;
    int tg  = tid >> 4;
    int s   = tid & 15;
    int token0 = blockIdx.x * 16;
    int token  = token0 + tg;

    const float4* xr = (const float4*)(x + (size_t)token * N_EMBED);
    uint2* xo = (uint2*)g_xhi + (size_t)token * 256;

    float acc[N_EXPERTS];
#pragma unroll
    for (int e = 0; e < N_EXPERTS; e++) acc[e] = 0.f;

#pragma unroll
    for (int i = 0; i < 16; i++) {
        int p = s + 16 * i;
        float4 v = xr[p];
        float vv[4] = {v.x, v.y, v.z, v.w};
        uint32_t h0 = (uint32_t)__half_as_ushort(__float2half(vv[0]))
                    | ((uint32_t)__half_as_ushort(__float2half(vv[1])) << 16);
        uint32_t h1 = (uint32_t)__half_as_ushort(__float2half(vv[2]))
                    | ((uint32_t)__half_as_ushort(__float2half(vv[3])) << 16);
        xo[p] = make_uint2(h0, h1);
#pragma unroll
        for (int q = 0; q < 4; q++) {
            const float* wr = wg + (p * 4 + q) * N_EXPERTS;
            float xv = vv[q];
#pragma unroll
            for (int e = 0; e < N_EXPERTS; e++) acc[e] += xv * wr[e];
        }
    }
#pragma unroll
    for (int off = 8; off > 0; off >>= 1) {
#pragma unroll
        for (int e = 0; e < N_EXPERTS; e++)
            acc[e] += __shfl_down_sync(0xffffffffu, acc[e], off, 16);
    }

    if (s == 0) {
        float fin[N_EXPERTS];
#pragma unroll
        for (int e = 0; e < N_EXPERTS; e++) fin[e] = acc[e] + bias[e];
        int e0 = 0; float v0 = fin[0];
#pragma unroll
        for (int e = 1; e < N_EXPERTS; e++)
            if (fin[e] > v0) { v0 = fin[e]; e0 = e; }
        int e1 = -1; float v1 = -3.0e38f;
#pragma unroll
        for (int e = 0; e < N_EXPERTS; e++)
            if (e != e0 && fin[e] > v1) { v1 = fin[e]; e1 = e; }

        float ex  = expf(v1 - v0);
        float inv = 1.0f / (1.0f + ex);
        float p0 = inv, p1 = ex * inv;

        g_probs[token * 2 + 0] = p0;
        g_probs[token * 2 + 1] = p1;
        if (probs_out) {
            probs_out[token * 2 + 0] = p0;
            probs_out[token * 2 + 1] = p1;
        }
        sassign[tg] = e0 | (e1 << 8);
    }
    __syncthreads();

    if (tid < N_EXPERTS) {
        int cnt = 0;
#pragma unroll
        for (int t = 0; t < 16; t++) {
            int a = sassign[t];
            cnt += ((a & 0xFF) == tid) + (((a >> 8) & 0xFF) == tid);
        }
        int base = atomicAdd(&g_counts[tid], cnt);
#pragma unroll
        for (int t = 0; t < 16; t++) {
            int a = sassign[t];
            if ((a & 0xFF) == tid)        g_list[tid * MAXCAP + base++] = (token0 + t) * 2;
            if (((a >> 8) & 0xFF) == tid) g_list[tid * MAXCAP + base++] = (token0 + t) * 2 + 1;
        }
    }
}

// ------------------------------------------------------------------ W[e][i][o] -> fp16 transposed [e][o][i]  [R10 verbatim]
__global__ __launch_bounds__(256) void convert_w_kernel(const float* __restrict__ w)
{
    __shared__ float sm[32][33];
    int e  = blockIdx.z;
    int i0 = blockIdx.x * 32;
    int o0 = blockIdx.y * 32;
    int tx = threadIdx.x, ty = threadIdx.y;   // (32, 8)

#pragma unroll
    for (int r = 0; r < 4; r++) {
        int i = i0 + ty + r * 8;
        sm[ty + r * 8][tx] = w[((size_t)e * N_EMBED + i) * N_EMBED + o0 + tx];
    }
    __syncthreads();
#pragma unroll
    for (int r = 0; r < 4; r++) {
        int o = o0 + ty + r * 8;
        float v = sm[tx][ty + r * 8];
        g_whi[((size_t)e * N_EMBED + o) * N_EMBED + i0 + tx] = __float2half(v);
    }
}

// ------------------------------------------------------------------ grouped GEMM: 64x128 tile, 256 threads, 8 warps of 32x32  [R10 mainloop]
__global__ void __launch_bounds__(256, 3) gemm_tc_kernel()
{
    extern __shared__ __align__(128) char smem[];
    int e   = blockIdx.z;
    int cnt = g_counts[e];
    int m0  = blockIdx.y * BM;
    if (m0 >= cnt) return;
    int n0  = blockIdx.x * BN;
    int tid = threadIdx.x, lane = tid & 31, wid = tid >> 5;
    int wm  = wid & 1;
    int wn  = wid >> 1;

    uint32_t sbase = smem_u32(smem);
    int* rows_s = (int*)smem;
    if (tid < BM) {
        int r = m0 + tid;
        rows_s[tid] = (r < cnt) ? g_list[e * MAXCAP + r] : -1;
    }
    __syncthreads();

    int r8 = tid >> 3, q = tid & 7;
    int arow0 = rows_s[r8], arow1 = rows_s[r8 + 32];
    int tok0 = (arow0 >= 0) ? (arow0 >> 1) : 0;
    int tok1 = (arow1 >= 0) ? (arow1 >> 1) : 0;
    int ap0 = (arow0 >= 0) ? 16 : 0;
    int ap1 = (arow1 >= 0) ? 16 : 0;
    const __half* aSrc0 = g_xhi + (size_t)tok0 * N_EMBED + q * 8;
    const __half* aSrc1 = g_xhi + (size_t)tok1 * N_EMBED + q * 8;
    const __half* bSrc  = g_whi + ((size_t)(e * N_EMBED + n0 + r8)) * N_EMBED + q * 8;
    uint32_t dstA = (uint32_t)(r8 * RSTRIDE + q * 16);
    uint32_t dstB = (uint32_t)(MAT_A + r8 * RSTRIDE + q * 16);

    uint32_t aAddr = sbase + SOFF_STAGE
                   + (uint32_t)((wm * 32 + (lane & 15)) * RSTRIDE + (lane >> 4) * 16);
    uint32_t bAddr = sbase + SOFF_STAGE + MAT_A
                   + (uint32_t)((wn * 32 + ((lane >> 4) << 3) + (lane & 7)) * RSTRIDE
                                + ((lane >> 3) & 1) * 16);

    float c[2][4][4];
#pragma unroll
    for (int mi = 0; mi < 2; mi++)
#pragma unroll
        for (int ni = 0; ni < 4; ni++)
#pragma unroll
            for (int r = 0; r < 4; r++) c[mi][ni][r] = 0.f;

    auto issue = [&](int it) {
        uint32_t st = sbase + SOFF_STAGE + (uint32_t)((it & 1) * STAGE_BYTES);
        int kt = it * BK;
        cp16(st + dstA,                aSrc0 + kt, ap0);
        cp16(st + dstA + 32 * RSTRIDE, aSrc1 + kt, ap1);
#pragma unroll
        for (int k = 0; k < 4; k++)
            cp16(st + dstB + (uint32_t)(k * 32 * RSTRIDE),
                 bSrc + kt + (size_t)k * 32 * N_EMBED, 16);
        asm volatile("cp.async.commit_group;" ::: "memory");
    };

    issue(0);
    issue(1);

    for (int it = 0; it < NK; it++) {
        if (it + 1 < NK) asm volatile("cp.async.wait_group 1;" ::: "memory");
        else             asm volatile("cp.async.wait_group 0;" ::: "memory");
        __syncthreads();

        uint32_t stA = (uint32_t)((it & 1) * STAGE_BYTES);
#pragma unroll
        for (int kk = 0; kk < 4; kk++) {
            uint32_t ko = (uint32_t)(kk * 32);
            uint32_t ah[2][4];
#pragma unroll
            for (int mi = 0; mi < 2; mi++)
                ldsm4(ah[mi], aAddr + stA + (uint32_t)(mi * 16 * RSTRIDE) + ko);
#pragma unroll
            for (int pr = 0; pr < 2; pr++) {
                uint32_t bh[4];
                ldsm4(bh, bAddr + stA + (uint32_t)(pr * 16 * RSTRIDE) + ko);
#pragma unroll
                for (int mi = 0; mi < 2; mi++) {
#pragma unroll
                    for (int t = 0; t < 2; t++) {
                        mma16816(c[mi][pr * 2 + t], ah[mi], &bh[t * 2]);
                    }
                }
            }
        }
        __syncthreads();
        if (it + 2 < NK) issue(it + 2);
    }

    // epilogue: fp16 stores (half2 per float pair)
#pragma unroll
    for (int mi = 0; mi < 2; mi++) {
#pragma unroll
        for (int h = 0; h < 2; h++) {
            int r = wm * 32 + mi * 16 + (lane >> 2) + h * 8;
            if (m0 + r < cnt) {
                int rowid = rows_s[r];
                __half* dst = g_outbuf + (size_t)rowid * N_EMBED
                            + n0 + wn * 32 + (lane & 3) * 2;
#pragma unroll
                for (int ni = 0; ni < 4; ni++) {
                    __half2 v = __floats2half2_rn(c[mi][ni][h * 2 + 0],
                                                  c[mi][ni][h * 2 + 1]);
                    *(__half2*)(dst + ni * 8) = v;
                }
            }
        }
    }
}

// ------------------------------------------------------------------ combine: y = p0*o0 + p1*o1 (fp16 inputs)
__global__ __launch_bounds__(256) void combine_kernel(float* __restrict__ y)
{
    int token = blockIdx.x;
    int tid   = threadIdx.x;
    float p0 = g_probs[token * 2 + 0];
    float p1 = g_probs[token * 2 + 1];
    const uint2* o0 = (const uint2*)(g_outbuf + (size_t)(token * 2) * N_EMBED);
    const uint2* o1 = o0 + (N_EMBED / 4);
    uint2 ua = o0[tid];     // 4 halves: elements tid*4 .. tid*4+3
    uint2 ub = o1[tid];
    float2 a0 = __half22float2(*(__half2*)&ua.x);
    float2 a1 = __half22float2(*(__half2*)&ua.y);
    float2 b0 = __half22float2(*(__half2*)&ub.x);
    float2 b1 = __half22float2(*(__half2*)&ub.y);
    float4 r = make_float4(p0 * a0.x + p1 * b0.x,
                           p0 * a0.y + p1 * b0.y,
                           p0 * a1.x + p1 * b1.x,
                           p0 * a1.y + p1 * b1.y);
    ((float4*)(y + (size_t)token * N_EMBED))[tid] = r;
}

// ------------------------------------------------------------------
extern "C" void kernel_launch(void* const* d_in, const int* in_sizes, int n_in,
                              void* d_out, int out_size)
{
    const float* x    = (const float*)d_in[0];
    const float* wg   = (const float*)d_in[1];
    const float* bias = (const float*)d_in[2];
    const float* w    = (const float*)d_in[3];
    float* out = (float*)d_out;

    const int Y_ELEMS = NTOK * N_EMBED;
    float* probs_out = (out_size >= Y_ELEMS + NTOK * TOPK) ? (out + Y_ELEMS) : nullptr;

    cudaFuncSetAttribute(gemm_tc_kernel,
                         cudaFuncAttributeMaxDynamicSharedMemorySize, SMEM_BYTES);

    init_kernel<<<1, 32>>>();
    gate_convert_kernel<<<NTOK / 16, 256>>>(x, wg, bias, probs_out);
    convert_w_kernel<<<dim3(32, 32, N_EXPERTS), dim3(32, 8)>>>(w);

    dim3 grid(N_EMBED / BN, MAXCAP / BM, N_EXPERTS);   // (8, 128, 8)
    gemm_tc_kernel<<<grid, 256, SMEM_BYTES>>>();

    combine_kernel<<<NTOK, 256>>>(out);
}